// round 9
// baseline (speedup 1.0000x reference)
#include <cuda_runtime.h>
#include <cuda_fp16.h>
#include <mma.h>
#include <cstdint>

using namespace nvcuda;

// ----------------------------------------------------------------------------
// out[64,14336](fp32) = (x[64,4096]*xs) @ (w[14336,4096]*ws)^T
// Inputs are int32 (harness promotes int8->int32), scales fp32, output fp32.
// R9: deep cp.async (3-stage) weight pipeline -> raw int32 smem; per-iter
// convert pass to fp16 tiles; X prefetched via registers (L2-resident);
// wmma HMMA core; direct fp32 stores. Grid 112 CTAs x 256 thr, 1 CTA/SM.
// ----------------------------------------------------------------------------

#define M_TOK   64
#define KDIM    4096
#define NOUT    14336
#define TILE_N  128
#define KC      64                         // K ints per pipeline iteration
#define ITERS   (KDIM / KC)                // 64
#define STAGES  3
#define RAW_ROW 272                        // bytes per raw W row (256 + 16 pad)
#define RAW_STAGE (TILE_N * RAW_ROW)       // 34816
#define WSTRIDE 72                         // halves per fp16 tile row (64 + 8)
#define WSM_OFF (STAGES * RAW_STAGE)                   // 104448
#define XSM_OFF (WSM_OFF + TILE_N * WSTRIDE * 2)       // 122880
#define SMEM_TOTAL (XSM_OFF + M_TOK * WSTRIDE * 2)     // 132096
#define OUT_ELEMS ((long)M_TOK * NOUT)     // 917504

__global__ void fill_kernel(float* out, long n) {
    long i = (long)blockIdx.x * blockDim.x + threadIdx.x;
    if (i < n) out[i] = 0.0f;
}

__device__ __forceinline__ uint32_t smem_u32(const void* p) {
    uint32_t a;
    asm("{ .reg .u64 t; cvta.to.shared.u64 t, %1; cvt.u32.u64 %0, t; }" : "=r"(a) : "l"(p));
    return a;
}

__device__ __forceinline__ void cp_async16(uint32_t smem_dst, const void* gmem_src) {
    asm volatile("cp.async.cg.shared.global [%0], [%1], 16;"
                 :: "r"(smem_dst), "l"(gmem_src) : "memory");
}

// 4 int32 -> 4 fp16 packed as uint2 (exact for |v| small)
__device__ __forceinline__ uint2 cvt4(uint4 v) {
    __half2 lo = __halves2half2(__int2half_rn((int)v.x), __int2half_rn((int)v.y));
    __half2 hi = __halves2half2(__int2half_rn((int)v.z), __int2half_rn((int)v.w));
    uint2 r;
    r.x = *reinterpret_cast<uint32_t*>(&lo);
    r.y = *reinterpret_cast<uint32_t*>(&hi);
    return r;
}

__global__ __launch_bounds__(256) void Model_89704686944640_kernel(
    const int* __restrict__ w, const int* __restrict__ x,
    const float* __restrict__ s0, const float* __restrict__ s1,
    float* __restrict__ out) {
    extern __shared__ char smem[];
    char* const wsm = smem + WSM_OFF;          // fp16 W tile [128][72]
    char* const xsm = smem + XSM_OFF;          // fp16 X tile [64][72]
    __half* const wsmh = reinterpret_cast<__half*>(wsm);
    __half* const xsmh = reinterpret_cast<__half*>(xsm);
    const uint32_t raw_base = smem_u32(smem);

    const int tid = threadIdx.x;
    const int wid = tid >> 5;
    const int fg = wid & 3;                    // feature group (4 x 32)
    const int th = wid >> 2;                   // token group (2 x 32)
    const int tile = blockIdx.x;
    const long wbase = (long)tile * TILE_N * KDIM;

    // convert-pass coordinates (bank-stagger-safe)
    const int c_row = tid & 127;               // W row
    const int c_h = tid >> 7;                  // which 128B half of the row

    wmma::fragment<wmma::accumulator, 16, 16, 16, float> c00, c01, c10, c11;
    wmma::fill_fragment(c00, 0.0f); wmma::fill_fragment(c01, 0.0f);
    wmma::fill_fragment(c10, 0.0f); wmma::fill_fragment(c11, 0.0f);

    // ---- prologue ----
    uint4 xr[4];                               // X registers for current iter
#pragma unroll
    for (int r = 0; r < 4; r++) {              // X iter 0: 64 rows x 16 chunks
        int idx = tid + r * 256;
        int row = idx >> 4, ci = (idx & 15) * 4;
        xr[r] = *reinterpret_cast<const uint4*>(x + (long)row * KDIM + ci);
    }
#pragma unroll
    for (int j = 0; j < STAGES; j++) {         // W stages 0..2
        const int koff = j * KC;
        const uint32_t sraw = raw_base + j * RAW_STAGE;
#pragma unroll
        for (int r = 0; r < 8; r++) {
            int idx = tid + r * 256;
            int row = idx >> 4, ci = (idx & 15) * 4;
            cp_async16(sraw + row * RAW_ROW + (idx & 15) * 16,
                       w + wbase + (long)row * KDIM + koff + ci);
        }
        asm volatile("cp.async.commit_group;" ::: "memory");
    }

    // ---- main loop ----
    for (int i = 0; i < ITERS; i++) {
        asm volatile("cp.async.wait_group %0;" :: "n"(STAGES - 1) : "memory");
        __syncthreads();   // stage i arrived; prev compute done (tiles reusable)

        const int s = i % STAGES;
        char* rawS = smem + s * RAW_STAGE;

        // convert W raw -> fp16 tile (each thread: one 128B half-row)
#pragma unroll
        for (int j = 0; j < 8; j++) {
            uint4 v = *reinterpret_cast<const uint4*>(rawS + c_row * RAW_ROW + c_h * 128 + j * 16);
            *reinterpret_cast<uint2*>(wsm + (c_row * WSTRIDE + c_h * 32 + j * 4) * 2) = cvt4(v);
        }
        // convert X regs -> fp16 tile
#pragma unroll
        for (int r = 0; r < 4; r++) {
            int idx = tid + r * 256;
            int row = idx >> 4, ci = (idx & 15) * 4;
            *reinterpret_cast<uint2*>(xsm + (row * WSTRIDE + ci) * 2) = cvt4(xr[r]);
        }
        __syncthreads();   // fp16 tiles ready; raw stage s free

        // refill: X regs for iter i+1; W stage for iter i+STAGES into raw s
        if (i + 1 < ITERS) {
            const int koff = (i + 1) * KC;
#pragma unroll
            for (int r = 0; r < 4; r++) {
                int idx = tid + r * 256;
                int row = idx >> 4, ci = (idx & 15) * 4;
                xr[r] = *reinterpret_cast<const uint4*>(x + (long)row * KDIM + koff + ci);
            }
        }
        if (i + STAGES < ITERS) {
            const int koff = (i + STAGES) * KC;
            const uint32_t sraw = raw_base + s * RAW_STAGE;
#pragma unroll
            for (int r = 0; r < 8; r++) {
                int idx = tid + r * 256;
                int row = idx >> 4, ci = (idx & 15) * 4;
                cp_async16(sraw + row * RAW_ROW + (idx & 15) * 16,
                           w + wbase + (long)row * KDIM + koff + ci);
            }
        }
        asm volatile("cp.async.commit_group;" ::: "memory");  // keep group count uniform

        // compute: 4 k-steps of 16
#pragma unroll
        for (int ks = 0; ks < 4; ks++) {
            wmma::fragment<wmma::matrix_b, 16, 16, 16, __half, wmma::col_major> b0, b1;
            wmma::load_matrix_sync(b0, wsmh + (fg * 32) * WSTRIDE + ks * 16, WSTRIDE);
            wmma::load_matrix_sync(b1, wsmh + (fg * 32 + 16) * WSTRIDE + ks * 16, WSTRIDE);
            wmma::fragment<wmma::matrix_a, 16, 16, 16, __half, wmma::row_major> a0, a1;
            wmma::load_matrix_sync(a0, xsmh + (th * 32) * WSTRIDE + ks * 16, WSTRIDE);
            wmma::load_matrix_sync(a1, xsmh + (th * 32 + 16) * WSTRIDE + ks * 16, WSTRIDE);
            wmma::mma_sync(c00, a0, b0, c00);
            wmma::mma_sync(c01, a0, b1, c01);
            wmma::mma_sync(c10, a1, b0, c10);
            wmma::mma_sync(c11, a1, b1, c11);
        }
    }

    // ---- epilogue: scale in-fragment, direct fp32 stores ----
    float sc = s0 ? s0[0] : 1.0f;
    if (s1) sc *= s1[0];
#pragma unroll
    for (int i = 0; i < c00.num_elements; i++) {
        c00.x[i] *= sc; c01.x[i] *= sc; c10.x[i] *= sc; c11.x[i] *= sc;
    }
    const long colbase = (long)tile * TILE_N + fg * 32;
    wmma::store_matrix_sync(out + (long)(th * 32) * NOUT + colbase,           c00, NOUT, wmma::mem_row_major);
    wmma::store_matrix_sync(out + (long)(th * 32) * NOUT + colbase + 16,      c01, NOUT, wmma::mem_row_major);
    wmma::store_matrix_sync(out + (long)(th * 32 + 16) * NOUT + colbase,      c10, NOUT, wmma::mem_row_major);
    wmma::store_matrix_sync(out + (long)(th * 32 + 16) * NOUT + colbase + 16, c11, NOUT, wmma::mem_row_major);
}

extern "C" void kernel_launch(void* const* d_in, const int* in_sizes, int n_in,
                              void* d_out, int out_size) {
    const int* w_q = nullptr;
    const int* x_q = nullptr;
    const float* s0 = nullptr;
    const float* s1 = nullptr;
    for (int i = 0; i < n_in; i++) {
        long n = in_sizes[i];
        if (n == (long)NOUT * KDIM) w_q = (const int*)d_in[i];
        else if (n == (long)M_TOK * KDIM) x_q = (const int*)d_in[i];
        else if (n <= 1) { if (!s0) s0 = (const float*)d_in[i]; else if (!s1) s1 = (const float*)d_in[i]; }
    }
    if (!x_q && n_in > 0) x_q = (const int*)d_in[0];
    if (!s0 && n_in > 1) s0 = (const float*)d_in[1];
    if (!w_q && n_in > 2) w_q = (const int*)d_in[2];
    if (!s1 && n_in > 3) s1 = (const float*)d_in[3];
    float* out = (float*)d_out;

    // fill only the tail beyond the logical output (if the buffer is larger)
    long tail = (long)out_size - OUT_ELEMS;
    if (tail > 0)
        fill_kernel<<<(int)((tail + 255) / 256), 256>>>(out + OUT_ELEMS, tail);

    cudaFuncSetAttribute(Model_89704686944640_kernel,
                         cudaFuncAttributeMaxDynamicSharedMemorySize, SMEM_TOTAL);
    Model_89704686944640_kernel<<<NOUT / TILE_N, 256, SMEM_TOTAL>>>(w_q, x_q, s0, s1, out);
}

// round 10
// speedup vs baseline: 1.4495x; 1.4495x over previous
#include <cuda_runtime.h>
#include <cuda_fp16.h>
#include <mma.h>
#include <cstdint>

using namespace nvcuda;

// ----------------------------------------------------------------------------
// out[64,14336](fp32) = (x[64,4096]*xs) @ (w[14336,4096]*ws)^T
// int32 inputs (harness promotes int8->int32), fp32 scales/output.
// R10: split-K x4 -> 448 CTAs (~3/SM resident, all 148 SMs busy). Per CTA:
// 2-stage cp.async raw int32 (W 128xKC + X 64xKC), convert pass -> fp16
// tiles, wmma HMMA core. Partials to __device__ scratch; reduce kernel
// applies scale and sums the 4 splits.
// ----------------------------------------------------------------------------

#define M_TOK   64
#define KDIM    4096
#define NOUT    14336
#define TILE_N  128
#define SPLITS  4
#define KR      (KDIM / SPLITS)            // 1024 per split
#define KC      32                         // K ints per iteration
#define ITERS   (KR / KC)                  // 32
#define RAW_ROW 144                        // bytes per raw row (128 + 16 pad)
#define W_RAW   (TILE_N * RAW_ROW)         // 18432
#define X_RAW   (M_TOK * RAW_ROW)          // 9216
#define STAGE_BYTES (W_RAW + X_RAW)        // 27648
#define WSTRIDE 40                         // halves per fp16 row (32 + 8 pad)
#define WSM_OFF (2 * STAGE_BYTES)                       // 55296
#define XSM_OFF (WSM_OFF + TILE_N * WSTRIDE * 2)        // 65536
#define SMEM_TOTAL (XSM_OFF + M_TOK * WSTRIDE * 2)      // 70656
#define OUT_ELEMS ((long)M_TOK * NOUT)     // 917504

__device__ float g_partial[SPLITS][M_TOK * NOUT];   // 14.7 MB scratch

__global__ void tail_fill_kernel(float* out, long n) {
    long i = (long)blockIdx.x * blockDim.x + threadIdx.x;
    if (i < n) out[i] = 0.0f;
}

// reduce: out = sc * (p0+p1+p2+p3), float4-vectorized
__global__ void reduce_kernel(float* __restrict__ out,
                              const float* __restrict__ s0,
                              const float* __restrict__ s1) {
    long i4 = (long)blockIdx.x * blockDim.x + threadIdx.x;
    if (i4 >= OUT_ELEMS / 4) return;
    float sc = (s0 ? s0[0] : 1.0f) * (s1 ? s1[0] : 1.0f);
    float4 a = reinterpret_cast<const float4*>(g_partial[0])[i4];
    float4 b = reinterpret_cast<const float4*>(g_partial[1])[i4];
    float4 c = reinterpret_cast<const float4*>(g_partial[2])[i4];
    float4 d = reinterpret_cast<const float4*>(g_partial[3])[i4];
    float4 r;
    r.x = sc * (a.x + b.x + c.x + d.x);
    r.y = sc * (a.y + b.y + c.y + d.y);
    r.z = sc * (a.z + b.z + c.z + d.z);
    r.w = sc * (a.w + b.w + c.w + d.w);
    reinterpret_cast<float4*>(out)[i4] = r;
}

__device__ __forceinline__ uint32_t smem_u32(const void* p) {
    uint32_t a;
    asm("{ .reg .u64 t; cvta.to.shared.u64 t, %1; cvt.u32.u64 %0, t; }" : "=r"(a) : "l"(p));
    return a;
}

__device__ __forceinline__ void cp_async16(uint32_t smem_dst, const void* gmem_src) {
    asm volatile("cp.async.cg.shared.global [%0], [%1], 16;"
                 :: "r"(smem_dst), "l"(gmem_src) : "memory");
}

// 4 int32 -> 4 fp16 packed as uint2 (exact for small ints)
__device__ __forceinline__ uint2 cvt4(uint4 v) {
    __half2 lo = __halves2half2(__int2half_rn((int)v.x), __int2half_rn((int)v.y));
    __half2 hi = __halves2half2(__int2half_rn((int)v.z), __int2half_rn((int)v.w));
    uint2 r;
    r.x = *reinterpret_cast<uint32_t*>(&lo);
    r.y = *reinterpret_cast<uint32_t*>(&hi);
    return r;
}

__global__ __launch_bounds__(256, 3) void Model_89704686944640_kernel(
    const int* __restrict__ w, const int* __restrict__ x) {
    extern __shared__ char smem[];
    __half* const wsmh = reinterpret_cast<__half*>(smem + WSM_OFF);  // [128][40]
    __half* const xsmh = reinterpret_cast<__half*>(smem + XSM_OFF);  // [64][40]
    const uint32_t raw_base = smem_u32(smem);

    const int tid = threadIdx.x;
    const int wid = tid >> 5;
    const int fg = wid & 3;                    // feature group (4 x 32)
    const int tg = wid >> 2;                   // token group (2 x 32)
    const int tile = blockIdx.x;
    const int split = blockIdx.y;
    const long wbase = (long)tile * TILE_N * KDIM;
    const int kbase0 = split * KR;

    wmma::fragment<wmma::accumulator, 16, 16, 16, float> c00, c01, c10, c11;
    wmma::fill_fragment(c00, 0.0f); wmma::fill_fragment(c01, 0.0f);
    wmma::fill_fragment(c10, 0.0f); wmma::fill_fragment(c11, 0.0f);

    // thread load coords: W 1024 chunks (4/thr), X 512 chunks (2/thr)
    // chunk idx -> row = idx>>3, ch = idx&7 (16B each, 8 per 128B row)
#pragma unroll
    for (int st = 0; st < 2; st++) {           // prologue: stages 0,1
        const int koff = kbase0 + st * KC;
        const uint32_t sraw = raw_base + st * STAGE_BYTES;
#pragma unroll
        for (int r = 0; r < 4; r++) {
            int idx = tid + r * 256;
            int row = idx >> 3, ch = idx & 7;
            cp_async16(sraw + row * RAW_ROW + ch * 16,
                       w + wbase + (long)row * KDIM + koff + ch * 4);
        }
#pragma unroll
        for (int r = 0; r < 2; r++) {
            int idx = tid + r * 256;
            int row = idx >> 3, ch = idx & 7;
            cp_async16(sraw + W_RAW + row * RAW_ROW + ch * 16,
                       x + (long)row * KDIM + koff + ch * 4);
        }
        asm volatile("cp.async.commit_group;" ::: "memory");
    }

    for (int i = 0; i < ITERS; i++) {
        asm volatile("cp.async.wait_group 1;" ::: "memory");
        __syncthreads();   // stage i%2 arrived; previous tiles consumed

        const int s = i & 1;
        char* rawS = smem + s * STAGE_BYTES;

        // convert raw int32 -> fp16 tiles
#pragma unroll
        for (int r = 0; r < 4; r++) {          // W: 1024 uint4 -> 4/thr
            int idx = tid + r * 256;
            int row = idx >> 3, c4 = (idx & 7) * 4;
            uint4 v = *reinterpret_cast<const uint4*>(rawS + row * RAW_ROW + (idx & 7) * 16);
            *reinterpret_cast<uint2*>(&wsmh[row * WSTRIDE + c4]) = cvt4(v);
        }
#pragma unroll
        for (int r = 0; r < 2; r++) {          // X: 512 uint4 -> 2/thr
            int idx = tid + r * 256;
            int row = idx >> 3, c4 = (idx & 7) * 4;
            uint4 v = *reinterpret_cast<const uint4*>(rawS + W_RAW + row * RAW_ROW + (idx & 7) * 16);
            *reinterpret_cast<uint2*>(&xsmh[row * WSTRIDE + c4]) = cvt4(v);
        }
        __syncthreads();   // tiles ready; raw stage s free

        if (i + 2 < ITERS) {                   // refill stage s for iter i+2
            const int koff = kbase0 + (i + 2) * KC;
            const uint32_t sraw = raw_base + s * STAGE_BYTES;
#pragma unroll
            for (int r = 0; r < 4; r++) {
                int idx = tid + r * 256;
                int row = idx >> 3, ch = idx & 7;
                cp_async16(sraw + row * RAW_ROW + ch * 16,
                           w + wbase + (long)row * KDIM + koff + ch * 4);
            }
#pragma unroll
            for (int r = 0; r < 2; r++) {
                int idx = tid + r * 256;
                int row = idx >> 3, ch = idx & 7;
                cp_async16(sraw + W_RAW + row * RAW_ROW + ch * 16,
                           x + (long)row * KDIM + koff + ch * 4);
            }
        }
        asm volatile("cp.async.commit_group;" ::: "memory");

        // compute: 2 k-steps of 16
#pragma unroll
        for (int ks = 0; ks < 2; ks++) {
            wmma::fragment<wmma::matrix_b, 16, 16, 16, __half, wmma::col_major> b0, b1;
            wmma::load_matrix_sync(b0, wsmh + (fg * 32) * WSTRIDE + ks * 16, WSTRIDE);
            wmma::load_matrix_sync(b1, wsmh + (fg * 32 + 16) * WSTRIDE + ks * 16, WSTRIDE);
            wmma::fragment<wmma::matrix_a, 16, 16, 16, __half, wmma::row_major> a0, a1;
            wmma::load_matrix_sync(a0, xsmh + (tg * 32) * WSTRIDE + ks * 16, WSTRIDE);
            wmma::load_matrix_sync(a1, xsmh + (tg * 32 + 16) * WSTRIDE + ks * 16, WSTRIDE);
            wmma::mma_sync(c00, a0, b0, c00);
            wmma::mma_sync(c01, a0, b1, c01);
            wmma::mma_sync(c10, a1, b0, c10);
            wmma::mma_sync(c11, a1, b1, c11);
        }
    }

    // ---- epilogue: store raw partials (scale applied in reduce) ----
    float* part = g_partial[split];
    const long colbase = (long)tile * TILE_N + fg * 32;
    wmma::store_matrix_sync(part + (long)(tg * 32) * NOUT + colbase,           c00, NOUT, wmma::mem_row_major);
    wmma::store_matrix_sync(part + (long)(tg * 32) * NOUT + colbase + 16,      c01, NOUT, wmma::mem_row_major);
    wmma::store_matrix_sync(part + (long)(tg * 32 + 16) * NOUT + colbase,      c10, NOUT, wmma::mem_row_major);
    wmma::store_matrix_sync(part + (long)(tg * 32 + 16) * NOUT + colbase + 16, c11, NOUT, wmma::mem_row_major);
}

extern "C" void kernel_launch(void* const* d_in, const int* in_sizes, int n_in,
                              void* d_out, int out_size) {
    const int* w_q = nullptr;
    const int* x_q = nullptr;
    const float* s0 = nullptr;
    const float* s1 = nullptr;
    for (int i = 0; i < n_in; i++) {
        long n = in_sizes[i];
        if (n == (long)NOUT * KDIM) w_q = (const int*)d_in[i];
        else if (n == (long)M_TOK * KDIM) x_q = (const int*)d_in[i];
        else if (n <= 1) { if (!s0) s0 = (const float*)d_in[i]; else if (!s1) s1 = (const float*)d_in[i]; }
    }
    if (!x_q && n_in > 0) x_q = (const int*)d_in[0];
    if (!s0 && n_in > 1) s0 = (const float*)d_in[1];
    if (!w_q && n_in > 2) w_q = (const int*)d_in[2];
    if (!s1 && n_in > 3) s1 = (const float*)d_in[3];
    float* out = (float*)d_out;

    long tail = (long)out_size - OUT_ELEMS;
    if (tail > 0)
        tail_fill_kernel<<<(int)((tail + 255) / 256), 256>>>(out + OUT_ELEMS, tail);

    cudaFuncSetAttribute(Model_89704686944640_kernel,
                         cudaFuncAttributeMaxDynamicSharedMemorySize, SMEM_TOTAL);
    dim3 grid(NOUT / TILE_N, SPLITS);
    Model_89704686944640_kernel<<<grid, 256, SMEM_TOTAL>>>(w_q, x_q);

    reduce_kernel<<<(int)((OUT_ELEMS / 4 + 255) / 256), 256>>>(out, s0, s1);
}